// round 17
// baseline (speedup 1.0000x reference)
#include <cuda_runtime.h>
#include <cuda_fp16.h>
#include <math.h>
#include <stdint.h>

#define B_   4
#define S_   2048
#define H_   1024
#define NH_  16
#define HD_  64
#define MTOT (B_ * S_)   // 8192
#define HEADN ((size_t)B_ * NH_ * S_ * HD_)

// ---------------- scratch (no allocs allowed) ----------------
__device__ __half g_xh[(size_t)MTOT * H_];
__device__ __half g_wqh[(size_t)H_ * H_];
__device__ __half g_wkh[(size_t)H_ * H_];
__device__ __half g_wvh[(size_t)H_ * H_];
__device__ __half g_woh[(size_t)H_ * H_];
__device__ __half g_qh[HEADN];
__device__ __half g_kh[HEADN];
__device__ __half g_vh[HEADN];
__device__ __half g_ch[(size_t)MTOT * H_];
__device__ float g_h[(size_t)MTOT * H_];      // pre-LN fp32

// ---------------- common PTX helpers ----------------
__device__ __forceinline__ void mma16816h(float* c, const uint32_t* a, const uint32_t* b) {
    asm volatile(
        "mma.sync.aligned.m16n8k16.row.col.f32.f16.f16.f32 "
        "{%0,%1,%2,%3}, {%4,%5,%6,%7}, {%8,%9}, {%0,%1,%2,%3};\n"
        : "+f"(c[0]), "+f"(c[1]), "+f"(c[2]), "+f"(c[3])
        : "r"(a[0]), "r"(a[1]), "r"(a[2]), "r"(a[3]), "r"(b[0]), "r"(b[1]));
}
__device__ __forceinline__ void ldsm_x4(uint32_t* r, uint32_t addr) {
    asm volatile(
        "ldmatrix.sync.aligned.m8n8.x4.shared.b16 {%0,%1,%2,%3}, [%4];\n"
        : "=r"(r[0]), "=r"(r[1]), "=r"(r[2]), "=r"(r[3]) : "r"(addr));
}
__device__ __forceinline__ void ldsm_x4_t(uint32_t* r, uint32_t addr) {
    asm volatile(
        "ldmatrix.sync.aligned.m8n8.x4.trans.shared.b16 {%0,%1,%2,%3}, [%4];\n"
        : "=r"(r[0]), "=r"(r[1]), "=r"(r[2]), "=r"(r[3]) : "r"(addr));
}
__device__ __forceinline__ uint32_t pack2h(float x, float y) {
    __half2 h2 = __floats2half2_rn(x, y);
    return *(uint32_t*)&h2;
}

// ---------------- prep: fp32 -> fp16 ----------------
__global__ __launch_bounds__(256) void split_x(
    const float4* __restrict__ src, uint2* __restrict__ dh, int n4)
{
    int i = blockIdx.x * blockDim.x + threadIdx.x;
    if (i >= n4) return;
    float4 f = src[i];
    dh[i] = make_uint2(pack2h(f.x, f.y), pack2h(f.z, f.w));
}
__global__ __launch_bounds__(256) void split_w4(
    const float4* __restrict__ w0, const float4* __restrict__ w1,
    const float4* __restrict__ w2, const float4* __restrict__ w3,
    uint2* __restrict__ d0, uint2* __restrict__ d1,
    uint2* __restrict__ d2, uint2* __restrict__ d3, int n4)
{
    int i = blockIdx.x * blockDim.x + threadIdx.x;
    if (i >= n4) return;
    const int m = blockIdx.y;
    const float4* src = (m == 0) ? w0 : (m == 1) ? w1 : (m == 2) ? w2 : w3;
    uint2* dst = (m == 0) ? d0 : (m == 1) ? d1 : (m == 2) ? d2 : d3;
    float4 f = src[i];
    dst[i] = make_uint2(pack2h(f.x, f.y), pack2h(f.z, f.w));
}

// ============================================================
//  fp16 tensor-core GEMM: C = A * W^T + bias  (unchanged)
// ============================================================
#define BM 128
#define BN 128
#define BK 32
#define LDS_PAD 8
#define LDK (BK + LDS_PAD)
#define G_ARR (2 * BM * LDK * 2)
#define GEMM_SMEM (2 * G_ARR)

#define QSCALE 0.1803368801111204f   // (1/8) * log2(e)

__global__ __launch_bounds__(256, 2) void gemm_pre(
    const __half* __restrict__ Ah_,
    const __half* __restrict__ Wh0, const __half* __restrict__ Wh1, const __half* __restrict__ Wh2,
    const float* __restrict__ bias0, const float* __restrict__ bias1, const float* __restrict__ bias2,
    __half* __restrict__ Oq, __half* __restrict__ Ok, __half* __restrict__ Ov,
    float* __restrict__ Cf, const float* __restrict__ resid, int qkv_layout)
{
    extern __shared__ char smem[];
    const int K = H_;
    const int z = blockIdx.z;
    const __half* Wh = (z == 0) ? Wh0 : (z == 1) ? Wh1 : Wh2;
    const float* bias = (z == 0) ? bias0 : (z == 1) ? bias1 : bias2;
    __half* Oc = (z == 0) ? Oq : (z == 1) ? Ok : Ov;
    const float scale = (qkv_layout && z == 0) ? QSCALE : 1.0f;

    __half* sA = (__half*)(smem);
    __half* sB = (__half*)(smem + G_ARR);

    const int tid  = threadIdx.x;
    const int warp = tid >> 5;
    const int lane = tid & 31;
    const int rowBase = blockIdx.y * BM;
    const int colBase = blockIdx.x * BN;

    const int m0 = (warp >> 1) * 32;
    const int n0 = (warp & 1) * 64;

    const int lrow = tid >> 1;
    const int lcol = (tid & 1) * 16;
    const __half* Ag = Ah_ + (size_t)(rowBase + lrow) * K + lcol;
    const __half* Wg = Wh + (size_t)(colBase + lrow) * K + lcol;

    const int a_row = m0 + ((lane >> 3) & 1) * 8 + (lane & 7);
    const int a_col = ((lane >> 4) & 1) * 8;
    const int b_row = n0 + ((lane >> 4) & 1) * 8 + (lane & 7);
    const int b_col = ((lane >> 3) & 1) * 8;

    const uint32_t bufStride = (uint32_t)(BM * LDK * 2);
    const uint32_t sAU = (uint32_t)__cvta_generic_to_shared(sA);
    const uint32_t sBU = (uint32_t)__cvta_generic_to_shared(sB);

    float acc[2][8][4];
#pragma unroll
    for (int i = 0; i < 2; i++)
#pragma unroll
        for (int j = 0; j < 8; j++)
#pragma unroll
            for (int r = 0; r < 4; r++) acc[i][j][r] = 0.f;

    uint4 ra[2], rb[2];
    ra[0] = *(const uint4*)(Ag);     ra[1] = *(const uint4*)(Ag + 8);
    rb[0] = *(const uint4*)(Wg);     rb[1] = *(const uint4*)(Wg + 8);
    {
        const int eo = lrow * LDK + lcol;
        *(uint4*)(sA + eo) = ra[0]; *(uint4*)(sA + eo + 8) = ra[1];
        *(uint4*)(sB + eo) = rb[0]; *(uint4*)(sB + eo + 8) = rb[1];
    }
    __syncthreads();

    int p = 0;
    for (int kt = 0; kt < K; kt += BK) {
        const bool hasNext = (kt + BK < K);
        if (hasNext) {
            ra[0] = *(const uint4*)(Ag + kt + BK);  ra[1] = *(const uint4*)(Ag + kt + BK + 8);
            rb[0] = *(const uint4*)(Wg + kt + BK);  rb[1] = *(const uint4*)(Wg + kt + BK + 8);
        }

        const uint32_t bufOff = (uint32_t)p * bufStride;
#pragma unroll
        for (int ks = 0; ks < 2; ks++) {
            const int kb = ks * 16;
            uint32_t ah[2][4], bh[8][2];
#pragma unroll
            for (int mi = 0; mi < 2; mi++) {
                uint32_t off = bufOff + (uint32_t)(((a_row + mi * 16) * LDK) + kb + a_col) * 2;
                ldsm_x4(ah[mi], sAU + off);
            }
#pragma unroll
            for (int pq = 0; pq < 4; pq++) {
                uint32_t off = bufOff + (uint32_t)(((b_row + pq * 16) * LDK) + kb + b_col) * 2;
                uint32_t t[4];
                ldsm_x4(t, sBU + off);
                bh[2 * pq][0] = t[0]; bh[2 * pq][1] = t[1];
                bh[2 * pq + 1][0] = t[2]; bh[2 * pq + 1][1] = t[3];
            }
#pragma unroll
            for (int nj = 0; nj < 8; nj++)
#pragma unroll
                for (int mi = 0; mi < 2; mi++)
                    mma16816h(acc[mi][nj], ah[mi], bh[nj]);
        }

        if (hasNext) {
            const int eo = (p ^ 1) * (BM * LDK) + lrow * LDK + lcol;
            *(uint4*)(sA + eo) = ra[0]; *(uint4*)(sA + eo + 8) = ra[1];
            *(uint4*)(sB + eo) = rb[0]; *(uint4*)(sB + eo + 8) = rb[1];
        }
        __syncthreads();
        p ^= 1;
    }

    const int g  = lane >> 2;
    const int t2 = (lane & 3) * 2;
#pragma unroll
    for (int mi = 0; mi < 2; mi++) {
#pragma unroll
        for (int nj = 0; nj < 8; nj++) {
            int n = colBase + n0 + nj * 8 + t2;
            float bia0 = bias[n], bia1 = bias[n + 1];
#pragma unroll
            for (int rr = 0; rr < 2; rr++) {
                int m = rowBase + m0 + mi * 16 + g + rr * 8;
                float v0 = acc[mi][nj][rr * 2 + 0] + bia0;
                float v1 = acc[mi][nj][rr * 2 + 1] + bia1;
                if (qkv_layout) {
                    int bb = m >> 11, ss = m & (S_ - 1);
                    int hh = n >> 6, dd = n & (HD_ - 1);
                    size_t off = ((((size_t)bb * NH_) + hh) * S_ + ss) * HD_ + dd;
                    *(uint32_t*)&Oc[off] = pack2h(v0 * scale, v1 * scale);
                } else {
                    const float2 rs = *(const float2*)&resid[(size_t)m * H_ + n];
                    *(float2*)&Cf[(size_t)m * H_ + n] = make_float2(v0 + rs.x, v1 + rs.y);
                }
            }
        }
    }
}

// ============================================================
//  fp16 flash attention: 128 q x 64 kv tiles, 4 warps x 32 q,
//  128 threads, 2 CTA/SM — halved LDSM redundancy.
// ============================================================
#define FLDV 72
#define F_ARR (2 * 64 * FLDV * 2)          // 18432 B (both buffers)
#define FLASH_SMEM (2 * F_ARR)             // 36864 B (K, V)

__global__ __launch_bounds__(128, 2) void flash_mma(
    const __half* __restrict__ Qh, const __half* __restrict__ Kgh,
    const __half* __restrict__ Vgh, __half* __restrict__ Ch)
{
    extern __shared__ char smem[];
    __half* Kh = (__half*)(smem);
    __half* Vh = (__half*)(smem + F_ARR);

    const int b = blockIdx.z;
    const int h = blockIdx.y;
    const int tid  = threadIdx.x;
    const int warp = tid >> 5;         // 0..3, owns q rows [32w, 32w+32)
    const int lane = tid & 31;
    const int q0 = blockIdx.x * 128;

    const size_t headBase = (((size_t)b * NH_ + h) * S_) * HD_;

    // cooperative K/V load: thread t -> row t>>1, half-cols (t&1)*32..+31
    const int lrow = tid >> 1;
    const int lcol = (tid & 1) * 32;

    const int b_row = ((lane >> 4) & 1) * 8 + (lane & 7);
    const int b_col = ((lane >> 3) & 1) * 8;
    const int v_row = ((lane >> 3) & 1) * 8 + (lane & 7);
    const int v_col = ((lane >> 4) & 1) * 8;

    const uint32_t bufStride = (uint32_t)(64 * FLDV * 2);
    const uint32_t sKh = (uint32_t)__cvta_generic_to_shared(Kh);
    const uint32_t sVh = (uint32_t)__cvta_generic_to_shared(Vh);

    const int g  = lane >> 2;
    const int t2 = (lane & 3) * 2;

    // ---- Q fragments (2 m-tiles per warp) straight from gmem ----
    uint32_t qh[4][2][4];
    {
#pragma unroll
        for (int mi = 0; mi < 2; mi++) {
            const __half* q0p = Qh + headBase + (size_t)(q0 + warp * 32 + mi * 16 + g) * HD_;
            const __half* q1p = q0p + 8 * HD_;
#pragma unroll
            for (int ks = 0; ks < 4; ks++) {
                int c = ks * 16 + t2;
                qh[ks][mi][0] = *(const uint32_t*)(q0p + c);
                qh[ks][mi][1] = *(const uint32_t*)(q1p + c);
                qh[ks][mi][2] = *(const uint32_t*)(q0p + c + 8);
                qh[ks][mi][3] = *(const uint32_t*)(q1p + c + 8);
            }
        }
    }

    float o[2][8][4];
#pragma unroll
    for (int mi = 0; mi < 2; mi++)
#pragma unroll
        for (int dn = 0; dn < 8; dn++)
#pragma unroll
            for (int e = 0; e < 4; e++) o[mi][dn][e] = 0.f;
    float mrun[2][2] = {{-1e30f, -1e30f}, {-1e30f, -1e30f}};
    float lrun[2][2] = {{0.f, 0.f}, {0.f, 0.f}};

    // ---- prologue: tile 0 -> regs -> buffer 0 ----
    uint4 kh2[4], vh2[4];
    {
        const __half* kg = Kgh + headBase + (size_t)lrow * HD_ + lcol;
        const __half* vg = Vgh + headBase + (size_t)lrow * HD_ + lcol;
#pragma unroll
        for (int i = 0; i < 4; i++) {
            kh2[i] = *(const uint4*)(kg + 8 * i);
            vh2[i] = *(const uint4*)(vg + 8 * i);
        }
        const int eo = lrow * FLDV + lcol;
#pragma unroll
        for (int i = 0; i < 4; i++) {
            *(uint4*)(Kh + eo + 8 * i) = kh2[i];
            *(uint4*)(Vh + eo + 8 * i) = vh2[i];
        }
    }
    __syncthreads();

    int p = 0;
    for (int j0 = 0; j0 < S_; j0 += 64) {
        const bool hasNext = (j0 + 64 < S_);
        if (hasNext) {
            const __half* kg = Kgh + headBase + (size_t)(j0 + 64 + lrow) * HD_ + lcol;
            const __half* vg = Vgh + headBase + (size_t)(j0 + 64 + lrow) * HD_ + lcol;
#pragma unroll
            for (int i = 0; i < 4; i++) {
                kh2[i] = *(const uint4*)(kg + 8 * i);
                vh2[i] = *(const uint4*)(vg + 8 * i);
            }
        }

        const uint32_t bufOff = (uint32_t)p * bufStride;

        // ---- S = Q K^T (log2 domain) ----
        float sacc[2][8][4];
#pragma unroll
        for (int mi = 0; mi < 2; mi++)
#pragma unroll
            for (int nj = 0; nj < 8; nj++)
#pragma unroll
                for (int e = 0; e < 4; e++) sacc[mi][nj][e] = 0.f;

#pragma unroll
        for (int ks = 0; ks < 4; ks++) {
            uint32_t bh[8][2];
#pragma unroll
            for (int pq = 0; pq < 4; pq++) {
                uint32_t off = bufOff + (uint32_t)(((pq * 16 + b_row) * FLDV) + ks * 16 + b_col) * 2;
                uint32_t t[4];
                ldsm_x4(t, sKh + off);
                bh[2 * pq][0] = t[0]; bh[2 * pq][1] = t[1];
                bh[2 * pq + 1][0] = t[2]; bh[2 * pq + 1][1] = t[3];
            }
#pragma unroll
            for (int nj = 0; nj < 8; nj++)
#pragma unroll
                for (int mi = 0; mi < 2; mi++)
                    mma16816h(sacc[mi][nj], qh[ks][mi], bh[nj]);
        }

        // ---- online softmax (base-2), rows per thread: mi x {g, g+8} ----
#pragma unroll
        for (int mi = 0; mi < 2; mi++) {
            float mloc[2] = {-1e30f, -1e30f};
#pragma unroll
            for (int nj = 0; nj < 8; nj++) {
                mloc[0] = fmaxf(mloc[0], fmaxf(sacc[mi][nj][0], sacc[mi][nj][1]));
                mloc[1] = fmaxf(mloc[1], fmaxf(sacc[mi][nj][2], sacc[mi][nj][3]));
            }
#pragma unroll
            for (int r = 0; r < 2; r++) {
                mloc[r] = fmaxf(mloc[r], __shfl_xor_sync(0xFFFFFFFFu, mloc[r], 1));
                mloc[r] = fmaxf(mloc[r], __shfl_xor_sync(0xFFFFFFFFu, mloc[r], 2));
            }
            float corr[2];
#pragma unroll
            for (int r = 0; r < 2; r++) {
                float mnew = fmaxf(mrun[mi][r], mloc[r]);
                corr[r] = exp2f(mrun[mi][r] - mnew);
                mrun[mi][r] = mnew;
            }
            float psum[2] = {0.f, 0.f};
#pragma unroll
            for (int nj = 0; nj < 8; nj++) {
                float p0 = exp2f(sacc[mi][nj][0] - mrun[mi][0]);
                float p1 = exp2f(sacc[mi][nj][1] - mrun[mi][0]);
                float p2 = exp2f(sacc[mi][nj][2] - mrun[mi][1]);
                float p3 = exp2f(sacc[mi][nj][3] - mrun[mi][1]);
                sacc[mi][nj][0] = p0; sacc[mi][nj][1] = p1;
                sacc[mi][nj][2] = p2; sacc[mi][nj][3] = p3;
                psum[0] += p0 + p1;
                psum[1] += p2 + p3;
            }
#pragma unroll
            for (int r = 0; r < 2; r++) {
                psum[r] += __shfl_xor_sync(0xFFFFFFFFu, psum[r], 1);
                psum[r] += __shfl_xor_sync(0xFFFFFFFFu, psum[r], 2);
                lrun[mi][r] = lrun[mi][r] * corr[r] + psum[r];
            }
#pragma unroll
            for (int dn = 0; dn < 8; dn++) {
                o[mi][dn][0] *= corr[0]; o[mi][dn][1] *= corr[0];
                o[mi][dn][2] *= corr[1]; o[mi][dn][3] *= corr[1];
            }
        }

        // ---- repack P -> A-frags ----
        uint32_t ph[4][2][4];
#pragma unroll
        for (int ks = 0; ks < 4; ks++)
#pragma unroll
            for (int mi = 0; mi < 2; mi++) {
                const float* c0 = sacc[mi][2 * ks];
                const float* c1 = sacc[mi][2 * ks + 1];
                ph[ks][mi][0] = pack2h(c0[0], c0[1]);
                ph[ks][mi][1] = pack2h(c0[2], c0[3]);
                ph[ks][mi][2] = pack2h(c1[0], c1[1]);
                ph[ks][mi][3] = pack2h(c1[2], c1[3]);
            }

        // ---- O += P V ----
#pragma unroll
        for (int ks = 0; ks < 4; ks++) {
            uint32_t vbh[8][2];
#pragma unroll
            for (int pq = 0; pq < 4; pq++) {
                uint32_t off = bufOff + (uint32_t)(((ks * 16 + v_row) * FLDV) + pq * 16 + v_col) * 2;
                uint32_t t[4];
                ldsm_x4_t(t, sVh + off);
                vbh[2 * pq][0] = t[0]; vbh[2 * pq][1] = t[1];
                vbh[2 * pq + 1][0] = t[2]; vbh[2 * pq + 1][1] = t[3];
            }
#pragma unroll
            for (int dn = 0; dn < 8; dn++)
#pragma unroll
                for (int mi = 0; mi < 2; mi++)
                    mma16816h(o[mi][dn], ph[ks][mi], vbh[dn]);
        }

        // ---- store prefetched tile into the other buffer ----
        if (hasNext) {
            const int eo = (p ^ 1) * (64 * FLDV) + lrow * FLDV + lcol;
#pragma unroll
            for (int i = 0; i < 4; i++) {
                *(uint4*)(Kh + eo + 8 * i) = kh2[i];
                *(uint4*)(Vh + eo + 8 * i) = vh2[i];
            }
        }
        __syncthreads();
        p ^= 1;
    }

    // ---- finalize: write ctx as fp16 [B,S,H] ----
#pragma unroll
    for (int mi = 0; mi < 2; mi++) {
        float inv0 = 1.0f / lrun[mi][0];
        float inv1 = 1.0f / lrun[mi][1];
#pragma unroll
        for (int dn = 0; dn < 8; dn++) {
            int d = h * HD_ + dn * 8 + t2;
            int m0g = q0 + warp * 32 + mi * 16 + g;
            size_t off0 = ((size_t)b * S_ + m0g) * H_ + d;
            size_t off1 = ((size_t)b * S_ + m0g + 8) * H_ + d;
            *(uint32_t*)&Ch[off0] = pack2h(o[mi][dn][0] * inv0, o[mi][dn][1] * inv0);
            *(uint32_t*)&Ch[off1] = pack2h(o[mi][dn][2] * inv1, o[mi][dn][3] * inv1);
        }
    }
}

// ---------------- layernorm (one block per row) --------------------------
__global__ __launch_bounds__(256) void layernorm_k(
    const float* __restrict__ hin, const float* __restrict__ gamma,
    const float* __restrict__ beta, float* __restrict__ out)
{
    const int row = blockIdx.x;
    const int t = threadIdx.x;
    const float* hp = hin + (size_t)row * H_;
    float* op = out + (size_t)row * H_;

    float4 x4 = ((const float4*)hp)[t];
    float sum = x4.x + x4.y + x4.z + x4.w;
    float sq  = x4.x * x4.x + x4.y * x4.y + x4.z * x4.z + x4.w * x4.w;

#pragma unroll
    for (int off = 16; off > 0; off >>= 1) {
        sum += __shfl_xor_sync(0xFFFFFFFFu, sum, off);
        sq  += __shfl_xor_sync(0xFFFFFFFFu, sq,  off);
    }
    __shared__ float ssum[8], ssq[8];
    const int wid = t >> 5, lid = t & 31;
    if (lid == 0) { ssum[wid] = sum; ssq[wid] = sq; }
    __syncthreads();
    if (wid == 0) {
        float a = (lid < 8) ? ssum[lid] : 0.f;
        float b = (lid < 8) ? ssq[lid]  : 0.f;
#pragma unroll
        for (int off = 4; off > 0; off >>= 1) {
            a += __shfl_xor_sync(0xFFFFFFFFu, a, off);
            b += __shfl_xor_sync(0xFFFFFFFFu, b, off);
        }
        if (lid == 0) { ssum[0] = a; ssq[0] = b; }
    }
    __syncthreads();
    const float mean = ssum[0] * (1.0f / H_);
    const float var  = ssq[0] * (1.0f / H_) - mean * mean;
    const float rstd = rsqrtf(var + 1e-12f);

    float4 g4 = ((const float4*)gamma)[t];
    float4 b4 = ((const float4*)beta)[t];
    float4 o4;
    o4.x = g4.x * (x4.x - mean) * rstd + b4.x;
    o4.y = g4.y * (x4.y - mean) * rstd + b4.y;
    o4.z = g4.z * (x4.z - mean) * rstd + b4.z;
    o4.w = g4.w * (x4.w - mean) * rstd + b4.w;
    ((float4*)op)[t] = o4;
}

// ---------------- launch ----------------
extern "C" void kernel_launch(void* const* d_in, const int* in_sizes, int n_in,
                              void* d_out, int out_size)
{
    const float* x     = (const float*)d_in[0];
    const float* wq    = (const float*)d_in[1];
    const float* bq    = (const float*)d_in[2];
    const float* wk    = (const float*)d_in[3];
    const float* bk    = (const float*)d_in[4];
    const float* wv    = (const float*)d_in[5];
    const float* bv    = (const float*)d_in[6];
    const float* wo    = (const float*)d_in[7];
    const float* bo    = (const float*)d_in[8];
    const float* gamma = (const float*)d_in[9];
    const float* beta  = (const float*)d_in[10];

    __half *xh, *wqh, *wkh, *wvh, *woh, *qh, *kh, *vh, *ch;
    float *hbuf;
    cudaGetSymbolAddress((void**)&xh,  g_xh);
    cudaGetSymbolAddress((void**)&wqh, g_wqh);
    cudaGetSymbolAddress((void**)&wkh, g_wkh);
    cudaGetSymbolAddress((void**)&wvh, g_wvh);
    cudaGetSymbolAddress((void**)&woh, g_woh);
    cudaGetSymbolAddress((void**)&qh,  g_qh);
    cudaGetSymbolAddress((void**)&kh,  g_kh);
    cudaGetSymbolAddress((void**)&vh,  g_vh);
    cudaGetSymbolAddress((void**)&ch,  g_ch);
    cudaGetSymbolAddress((void**)&hbuf, g_h);

    cudaFuncSetAttribute(gemm_pre,
                         cudaFuncAttributeMaxDynamicSharedMemorySize, GEMM_SMEM);
    cudaFuncSetAttribute(flash_mma,
                         cudaFuncAttributeMaxDynamicSharedMemorySize, FLASH_SMEM);

    // ---- prep: fp32 -> fp16 (2 launches) ----
    {
        const int XN4 = MTOT * H_ / 4;
        const int WN4 = H_ * H_ / 4;
        split_x<<<(XN4 + 255) / 256, 256>>>((const float4*)x, (uint2*)xh, XN4);
        split_w4<<<dim3((WN4 + 255) / 256, 4), 256>>>(
            (const float4*)wq, (const float4*)wk, (const float4*)wv, (const float4*)wo,
            (uint2*)wqh, (uint2*)wkh, (uint2*)wvh, (uint2*)woh, WN4);
    }

    // ---- fused QKV projections ----
    gemm_pre<<<dim3(H_ / BN, MTOT / BM, 3), 256, GEMM_SMEM>>>(
        xh, wqh, wkh, wvh, bq, bk, bv, qh, kh, vh, nullptr, nullptr, 1);

    // ---- flash attention (4 warps x 32 q rows) ----
    flash_mma<<<dim3(S_ / 128, NH_, B_), 128, FLASH_SMEM>>>(qh, kh, vh, ch);

    // ---- output projection + residual (fp32 out) ----
    gemm_pre<<<dim3(H_ / BN, MTOT / BM, 1), 256, GEMM_SMEM>>>(
        ch, woh, woh, woh, bo, bo, bo, nullptr, nullptr, nullptr, hbuf, x, 0);

    layernorm_k<<<MTOT, 256>>>(hbuf, gamma, beta, (float*)d_out);
}